// round 7
// baseline (speedup 1.0000x reference)
#include <cuda_runtime.h>

// FilterbankAttention v2 (de-risked): out[b, n*64+m] = gamma*sum F_Y[n,a] X[a,c] F_X[m,c]
// Banded Gaussian filterbanks (Wr<=32, exact global-sum normalization),
// stage1 from global (L1-cached), Tt in static smem, packed fma.rn.f32x2.
// One CTA per (image, src) task. No dynamic smem, no cp.async.

#define TP 65
#define NTHREADS 512

__device__ __align__(16) float d_FYb[2048];   // [g(16)][j(32)][ni(4)] gamma/SY folded
__device__ __align__(16) float d_FXb[2048];   // [g(16)][j(32)][ni(4)] 1/SX folded
__device__ int d_gsY[16];
__device__ int d_gsX[16];
__device__ int d_Wr;

static __device__ __forceinline__ unsigned long long pk2(float a, float b) {
    unsigned long long r;
    asm("mov.b64 %0, {%1,%2};" : "=l"(r) : "f"(a), "f"(b));
    return r;
}
static __device__ __forceinline__ void upk2(unsigned long long v, float &a, float &b) {
    asm("mov.b64 {%0,%1}, %2;" : "=f"(a), "=f"(b) : "l"(v));
}
static __device__ __forceinline__ void ffma2(unsigned long long &d,
                                             unsigned long long a,
                                             unsigned long long b) {
    asm("fma.rn.f32x2 %0, %1, %2, %0;" : "+l"(d) : "l"(a), "l"(b));
}

// ---------------------------------------------------------------------------
// Setup: one block. params = h[0] @ W^T + b, scalars, exact global sums,
// band width Wr, per-group window starts, banded filter tables.
// ---------------------------------------------------------------------------
__global__ void fb_setup_kernel(const float *__restrict__ h,
                                const float *__restrict__ Ww,
                                const float *__restrict__ Wb) {
    __shared__ float sp[5];
    __shared__ float sc[8];
    __shared__ int   sgsY[16], sgsX[16], sWr;
    __shared__ float ry[16], rx[16];

    const int tid = threadIdx.x, wid = tid >> 5, lane = tid & 31;

    if (wid < 5) {
        float s = 0.0f;
        for (int k = lane; k < 512; k += 32) s += h[k] * Ww[wid * 512 + k];
        #pragma unroll
        for (int o = 16; o; o >>= 1) s += __shfl_down_sync(0xffffffffu, s, o);
        if (lane == 0) sp[wid] = s + Wb[wid];
    }
    __syncthreads();

    if (tid == 0) {
        float var   = expf(sp[2] + 1e-8f);
        float dd    = expf(sp[3]) * (127.0f / 63.0f);
        float gX    = 129.0f * (sp[0] + 1.0f) * 0.5f;
        float gY    = 129.0f * (sp[1] + 1.0f) * 0.5f;
        float gamma = expf(sp[4]);
        float inv2v = 0.5f / var;
        float r    = sqrtf(41.45f * var);          // exp(-r^2/2var)=1e-9
        float half = r + 1.5f * dd + 1.0f;         // group of 4 filters spans 3d
        int Wr = (int)ceilf(2.0f * half);
        Wr = (Wr + 3) & ~3;
        if (Wr < 8)  Wr = 8;
        if (Wr > 32) Wr = 32;
        sWr = Wr;
        sc[0] = inv2v; sc[1] = dd; sc[2] = gY; sc[3] = gX; sc[6] = gamma;
        for (int g = 0; g < 16; g++) {
            float cY = gY + ((float)(4 * g) - 31.0f) * dd;
            int s = __float2int_rn(cY) - Wr / 2;
            sgsY[g] = max(0, min(128 - Wr, s));
            float cX = gX + ((float)(4 * g) - 31.0f) * dd;
            int sx = __float2int_rn(cX) - Wr / 2;
            sgsX[g] = max(0, min(128 - Wr, sx));
        }
    }
    __syncthreads();

    const float inv2v = sc[0], dd = sc[1], gY = sc[2], gX = sc[3];

    float sy = 0.0f, sx = 0.0f;          // exact global sums, full 64x128 banks
    for (int i = tid; i < 8192; i += NTHREADS) {
        int n = i >> 7, a = i & 127;
        float muY = gY + ((float)n - 32.5f) * dd;
        float muX = gX + ((float)n - 32.5f) * dd;
        float dy = (float)a - muY, dx = (float)a - muX;
        sy += expf(-dy * dy * inv2v);
        sx += expf(-dx * dx * inv2v);
    }
    #pragma unroll
    for (int o = 16; o; o >>= 1) {
        sy += __shfl_down_sync(0xffffffffu, sy, o);
        sx += __shfl_down_sync(0xffffffffu, sx, o);
    }
    if (lane == 0) { ry[wid] = sy; rx[wid] = sx; }
    __syncthreads();
    if (tid == 0) {
        float SY = 0.0f, SX = 0.0f;
        for (int w = 0; w < 16; w++) { SY += ry[w]; SX += rx[w]; }
        sc[4] = sc[6] / SY;
        sc[5] = 1.0f / SX;
    }
    __syncthreads();

    const float fyS = sc[4], fxS = sc[5];
    const int WrL = sWr;

    for (int i = tid; i < 2048; i += NTHREADS) {
        int g = i >> 7, rem = i & 127, j = rem >> 2, ni = rem & 3;
        int n = 4 * g + ni;
        float vy = 0.0f, vx = 0.0f;
        if (j < WrL) {
            float muY = gY + ((float)n - 32.5f) * dd;
            float dy = (float)(sgsY[g] + j) - muY;
            vy = expf(-dy * dy * inv2v) * fyS;
            float muX = gX + ((float)n - 32.5f) * dd;
            float dx = (float)(sgsX[g] + j) - muX;
            vx = expf(-dx * dx * inv2v) * fxS;
        }
        d_FYb[i] = vy;
        d_FXb[i] = vx;
    }
    if (tid < 16) { d_gsY[tid] = sgsY[tid]; d_gsX[tid] = sgsX[tid]; }
    if (tid == 0) d_Wr = sWr;
}

// ---------------------------------------------------------------------------
// Main: one CTA per (image, src) task. grid.x = 2*batch.
// ---------------------------------------------------------------------------
__global__ void __launch_bounds__(NTHREADS)
fb_main_kernel(const float *__restrict__ x, const float *__restrict__ xh,
               float *__restrict__ out) {
    __shared__ float Tt[128 * TP];     // 33280 B

    const int tid = threadIdx.x, wid = tid >> 5, lane = tid & 31;
    const int t = blockIdx.x;
    const int Wr = d_Wr;

    const float *Xg = ((t & 1) ? xh : x) + (size_t)(t >> 1) * 16384;

    // stage 1: Tt[c][n] = sum_a FY[n][a] * X[a][c]   (warp = group of 4 n's)
    {
        const int g  = wid;
        const int aB = d_gsY[g];
        const float4 *Fv = reinterpret_cast<const float4 *>(d_FYb) + g * 32;
        unsigned long long acc[4][2];
        #pragma unroll
        for (int i = 0; i < 4; i++) { acc[i][0] = 0ull; acc[i][1] = 0ull; }
        const float *Xb = Xg + lane;
        #pragma unroll 4
        for (int j = 0; j < Wr; j++) {
            const float *xr = Xb + (aB + j) * 128;
            unsigned long long xA = pk2(__ldg(xr),      __ldg(xr + 32));
            unsigned long long xB = pk2(__ldg(xr + 64), __ldg(xr + 96));
            float4 f = __ldg(Fv + j);
            unsigned long long f0 = pk2(f.x, f.x), f1 = pk2(f.y, f.y);
            unsigned long long f2 = pk2(f.z, f.z), f3 = pk2(f.w, f.w);
            ffma2(acc[0][0], xA, f0); ffma2(acc[0][1], xB, f0);
            ffma2(acc[1][0], xA, f1); ffma2(acc[1][1], xB, f1);
            ffma2(acc[2][0], xA, f2); ffma2(acc[2][1], xB, f2);
            ffma2(acc[3][0], xA, f3); ffma2(acc[3][1], xB, f3);
        }
        #pragma unroll
        for (int ni = 0; ni < 4; ni++) {
            float v0, v1, v2, v3;
            upk2(acc[ni][0], v0, v1);
            upk2(acc[ni][1], v2, v3);
            const int col = 4 * wid + ni;
            Tt[(lane     ) * TP + col] = v0;
            Tt[(lane + 32) * TP + col] = v1;
            Tt[(lane + 64) * TP + col] = v2;
            Tt[(lane + 96) * TP + col] = v3;
        }
    }
    __syncthreads();

    // stage 2: out[n][m] = sum_c Tt[c][n] * FX[m][c]   (warp = group of 4 m's)
    {
        const int gm = wid;
        const int cB = d_gsX[gm];
        const float4 *Fv = reinterpret_cast<const float4 *>(d_FXb) + gm * 32;
        unsigned long long acc[4] = {0ull, 0ull, 0ull, 0ull};
        #pragma unroll 4
        for (int j = 0; j < Wr; j++) {
            const float *tr = Tt + (cB + j) * TP + lane;
            unsigned long long tp = pk2(tr[0], tr[32]);   // n=lane, n=lane+32
            float4 f = __ldg(Fv + j);
            ffma2(acc[0], tp, pk2(f.x, f.x));
            ffma2(acc[1], tp, pk2(f.y, f.y));
            ffma2(acc[2], tp, pk2(f.z, f.z));
            ffma2(acc[3], tp, pk2(f.w, f.w));
        }
        float a0, a1, a2, a3, b0, b1, b2, b3;
        upk2(acc[0], a0, b0); upk2(acc[1], a1, b1);
        upk2(acc[2], a2, b2); upk2(acc[3], a3, b3);
        float *ob = out + (size_t)(t >> 1) * 8192 + (size_t)(t & 1) * 4096 + gm * 4;
        *reinterpret_cast<float4 *>(ob + (size_t)lane * 64) =
            make_float4(a0, a1, a2, a3);
        *reinterpret_cast<float4 *>(ob + (size_t)(lane + 32) * 64) =
            make_float4(b0, b1, b2, b3);
    }
}

extern "C" void kernel_launch(void* const* d_in, const int* in_sizes, int n_in,
                              void* d_out, int out_size) {
    const float *x  = (const float *)d_in[0];
    const float *xh = (const float *)d_in[1];
    const float *h  = (const float *)d_in[2];
    const float *Ww = (const float *)d_in[3];
    const float *Wb = (const float *)d_in[4];
    float *out = (float *)d_out;

    const int batch   = in_sizes[0] / 16384;
    const int n_tasks = 2 * batch;

    fb_setup_kernel<<<1, NTHREADS>>>(h, Ww, Wb);
    fb_main_kernel<<<n_tasks, NTHREADS>>>(x, xh, out);
}

// round 9
// speedup vs baseline: 1.0948x; 1.0948x over previous
#include <cuda_runtime.h>

// FilterbankAttention v3: 64-bit datapath.
// out[b, n*64+m] = gamma * sum_{a,c} F_Y[n,a] X[a,c] F_X[m,c]  (+x_hat half)
// Banded Gaussian filterbanks, exact global-sum normalization.
// Stage1: X via LDG.64 pairs, FY pre-duplicated ull table, acc in f32x2.
// T2[cp][n] ull in smem (stride 65). Stage2: paired-c accumulation, final hadd.

#define NTHREADS 512
#define NTH_SETUP 1024
typedef unsigned long long ull;

__device__ __align__(16) ull d_FYp[2048];   // [g16][j32][ni4]  (f,f), gamma/SY folded
__device__ __align__(16) ull d_FXp[1024];   // [g16][jp16][ni4] (f2jp, f2jp+1), 1/SX folded
__device__ int d_gsY[16];
__device__ int d_gsX2[16];   // even window start / 2
__device__ int d_Wr;

static __device__ __forceinline__ void upk2(ull v, float &a, float &b) {
    asm("mov.b64 {%0,%1}, %2;" : "=f"(a), "=f"(b) : "l"(v));
}
static __device__ __forceinline__ void ffma2(ull &d, ull a, ull b) {
    asm("fma.rn.f32x2 %0, %1, %2, %0;" : "+l"(d) : "l"(a), "l"(b));
}
static __device__ __forceinline__ float hadd(ull v) {
    float a, b; upk2(v, a, b); return a + b;
}

// ---------------------------------------------------------------------------
// Setup: one block, 1024 threads.
// ---------------------------------------------------------------------------
__global__ void __launch_bounds__(NTH_SETUP)
fb_setup_kernel(const float *__restrict__ h, const float *__restrict__ Ww,
                const float *__restrict__ Wb) {
    __shared__ float sp[5];
    __shared__ float sc[8];   // 0:inv2v 1:d 2:gY 3:gX 4:gamma/SY 5:1/SX 6:gamma
    __shared__ int   sgsY[16], sgsX[16], sWr;
    __shared__ float ry[32], rx[32];

    const int tid = threadIdx.x, wid = tid >> 5, lane = tid & 31;

    if (wid < 5) {                                   // params = h[0] @ W^T + b
        float s = 0.0f;
        for (int k = lane; k < 512; k += 32) s += h[k] * Ww[wid * 512 + k];
        #pragma unroll
        for (int o = 16; o; o >>= 1) s += __shfl_down_sync(0xffffffffu, s, o);
        if (lane == 0) sp[wid] = s + Wb[wid];
    }
    __syncthreads();

    if (tid == 0) {
        float var   = expf(sp[2] + 1e-8f);
        float dd    = expf(sp[3]) * (127.0f / 63.0f);
        float gX    = 129.0f * (sp[0] + 1.0f) * 0.5f;
        float gY    = 129.0f * (sp[1] + 1.0f) * 0.5f;
        float gamma = expf(sp[4]);
        float inv2v = 0.5f / var;
        float r    = sqrtf(34.5f * var);             // exp(-r^2/2var) ~ 3e-8
        float half = r + 1.5f * dd + 2.0f;           // group span + even-align margin
        int Wr = (int)ceilf(2.0f * half);
        Wr = (Wr + 3) & ~3;
        if (Wr < 8)  Wr = 8;
        if (Wr > 32) Wr = 32;
        sWr = Wr;
        sc[0] = inv2v; sc[1] = dd; sc[2] = gY; sc[3] = gX; sc[6] = gamma;
        for (int g = 0; g < 16; g++) {
            float cY = gY + ((float)(4 * g) - 31.0f) * dd;
            int s = __float2int_rn(cY) - Wr / 2;
            sgsY[g] = max(0, min(128 - Wr, s));
            float cX = gX + ((float)(4 * g) - 31.0f) * dd;
            int sx = (__float2int_rn(cX) - Wr / 2) & ~1;   // even for pairing
            sgsX[g] = max(0, min(128 - Wr, sx));
        }
    }
    __syncthreads();

    const float inv2v = sc[0], dd = sc[1], gY = sc[2], gX = sc[3];

    float sy = 0.0f, sx = 0.0f;        // exact global sums, full 64x128 banks
    for (int i = tid; i < 8192; i += NTH_SETUP) {
        int n = i >> 7, a = i & 127;
        float muY = gY + ((float)n - 32.5f) * dd;
        float muX = gX + ((float)n - 32.5f) * dd;
        float dy = (float)a - muY, dx = (float)a - muX;
        sy += expf(-dy * dy * inv2v);
        sx += expf(-dx * dx * inv2v);
    }
    #pragma unroll
    for (int o = 16; o; o >>= 1) {
        sy += __shfl_down_sync(0xffffffffu, sy, o);
        sx += __shfl_down_sync(0xffffffffu, sx, o);
    }
    if (lane == 0) { ry[wid] = sy; rx[wid] = sx; }
    __syncthreads();
    if (tid == 0) {
        float SY = 0.0f, SX = 0.0f;
        for (int w = 0; w < NTH_SETUP / 32; w++) { SY += ry[w]; SX += rx[w]; }
        sc[4] = sc[6] / SY;
        sc[5] = 1.0f / SX;
    }
    __syncthreads();

    const float fyS = sc[4], fxS = sc[5];
    const int Wr = sWr;

    // FY duplicated-pair table [g][j][ni]
    for (int i = tid; i < 2048; i += NTH_SETUP) {
        int g = i >> 7, rem = i & 127, j = rem >> 2, ni = rem & 3;
        int n = 4 * g + ni;
        float vy = 0.0f;
        if (j < Wr) {
            float muY = gY + ((float)n - 32.5f) * dd;
            float dy = (float)(sgsY[g] + j) - muY;
            vy = expf(-dy * dy * inv2v) * fyS;
        }
        unsigned u = __float_as_uint(vy);
        d_FYp[i] = (ull)u | ((ull)u << 32);
    }
    // FX adjacent-pair table [g][jp][ni]
    for (int i = tid; i < 1024; i += NTH_SETUP) {
        int g = i >> 6, rem = i & 63, jp = rem >> 2, ni = rem & 3;
        int n = 4 * g + ni;
        float muX = gX + ((float)n - 32.5f) * dd;
        float v0 = 0.0f, v1 = 0.0f;
        int c0 = sgsX[g] + 2 * jp;
        if (2 * jp < Wr) {
            float dx0 = (float)c0 - muX;
            float dx1 = (float)(c0 + 1) - muX;
            v0 = expf(-dx0 * dx0 * inv2v) * fxS;
            v1 = expf(-dx1 * dx1 * inv2v) * fxS;
        }
        d_FXp[i] = (ull)__float_as_uint(v0) | ((ull)__float_as_uint(v1) << 32);
    }
    if (tid < 16) { d_gsY[tid] = sgsY[tid]; d_gsX2[tid] = sgsX[tid] >> 1; }
    if (tid == 0) d_Wr = sWr;
}

// ---------------------------------------------------------------------------
// Main: one CTA per (image, src) task. grid.x = 2*batch.
// ---------------------------------------------------------------------------
__global__ void __launch_bounds__(NTHREADS)
fb_main_kernel(const float *__restrict__ x, const float *__restrict__ xh,
               float *__restrict__ out) {
    __shared__ ull T2[64 * 65];        // [cp 0..63][n 0..63] stride 65 -> 33280 B

    const int wid = threadIdx.x >> 5, lane = threadIdx.x & 31;
    const int t = blockIdx.x;
    const int Wr = d_Wr;

    const float *Xg = ((t & 1) ? xh : x) + (size_t)(t >> 1) * 16384;

    // stage 1: T2[cp][n] = pair_c { sum_a FY[n][a] * X[a][c] }
    {
        const int aB = d_gsY[wid];
        const ulonglong2 *Fp =
            reinterpret_cast<const ulonglong2 *>(d_FYp) + wid * 64;
        ull acc[4][2];
        #pragma unroll
        for (int i = 0; i < 4; i++) { acc[i][0] = 0ull; acc[i][1] = 0ull; }
        const ull *Xr = reinterpret_cast<const ull *>(Xg) + (size_t)aB * 64 + lane;
        #pragma unroll 4
        for (int j = 0; j < Wr; j++) {
            ull xA = __ldg(Xr);            // c = 2L, 2L+1
            ull xB = __ldg(Xr + 32);       // c = 2L+64, 2L+65
            Xr += 64;
            ulonglong2 f01 = __ldg(Fp + 2 * j);
            ulonglong2 f23 = __ldg(Fp + 2 * j + 1);
            ffma2(acc[0][0], xA, f01.x); ffma2(acc[0][1], xB, f01.x);
            ffma2(acc[1][0], xA, f01.y); ffma2(acc[1][1], xB, f01.y);
            ffma2(acc[2][0], xA, f23.x); ffma2(acc[2][1], xB, f23.x);
            ffma2(acc[3][0], xA, f23.y); ffma2(acc[3][1], xB, f23.y);
        }
        #pragma unroll
        for (int ni = 0; ni < 4; ni++) {
            const int n = 4 * wid + ni;
            T2[lane * 65 + n]        = acc[ni][0];   // cp = L
            T2[(lane + 32) * 65 + n] = acc[ni][1];   // cp = L+32
        }
    }
    __syncthreads();

    // stage 2: out[n][m] = sum_cp hadd( T2[cp][n] * FXpair[m][cp] )
    {
        const int gm = wid;
        const int cB2 = d_gsX2[gm];
        const ulonglong2 *Fp =
            reinterpret_cast<const ulonglong2 *>(d_FXp) + gm * 32;
        ull accA[4] = {0ull, 0ull, 0ull, 0ull};   // n = lane
        ull accB[4] = {0ull, 0ull, 0ull, 0ull};   // n = lane+32
        const int half = Wr >> 1;
        #pragma unroll 2
        for (int jp = 0; jp < half; jp++) {
            const ull *tr = T2 + (cB2 + jp) * 65;
            ull tA = tr[lane];
            ull tB = tr[lane + 32];
            ulonglong2 f01 = __ldg(Fp + 2 * jp);
            ulonglong2 f23 = __ldg(Fp + 2 * jp + 1);
            ffma2(accA[0], tA, f01.x); ffma2(accB[0], tB, f01.x);
            ffma2(accA[1], tA, f01.y); ffma2(accB[1], tB, f01.y);
            ffma2(accA[2], tA, f23.x); ffma2(accB[2], tB, f23.x);
            ffma2(accA[3], tA, f23.y); ffma2(accB[3], tB, f23.y);
        }
        float *ob = out + (size_t)(t >> 1) * 8192 + (size_t)(t & 1) * 4096 + gm * 4;
        *reinterpret_cast<float4 *>(ob + (size_t)lane * 64) =
            make_float4(hadd(accA[0]), hadd(accA[1]), hadd(accA[2]), hadd(accA[3]));
        *reinterpret_cast<float4 *>(ob + (size_t)(lane + 32) * 64) =
            make_float4(hadd(accB[0]), hadd(accB[1]), hadd(accB[2]), hadd(accB[3]));
    }
}

extern "C" void kernel_launch(void* const* d_in, const int* in_sizes, int n_in,
                              void* d_out, int out_size) {
    const float *x  = (const float *)d_in[0];
    const float *xh = (const float *)d_in[1];
    const float *h  = (const float *)d_in[2];
    const float *Ww = (const float *)d_in[3];
    const float *Wb = (const float *)d_in[4];
    float *out = (float *)d_out;

    const int batch   = in_sizes[0] / 16384;
    const int n_tasks = 2 * batch;

    fb_setup_kernel<<<1, NTH_SETUP>>>(h, Ww, Wb);
    fb_main_kernel<<<n_tasks, NTHREADS>>>(x, xh, out);
}